// round 13
// baseline (speedup 1.0000x reference)
#include <cuda_runtime.h>
#include <cstdint>

// LIF forward scan, 4 time steps. x/out: [4, N] fp32, N = 8,388,608.
// Forward value of the surrogate spike == hard threshold (mem > 0.5).
// HBM-bound streaming: 134 MiB read + 134 MiB write.
//
// R12: best-known flat config (1024-thr blocks, 30 regs, __ldcs loads)
// with ONE probe: stores switch .cs -> .wt (write-through). Theory: the
// constant ~7.5us bench-vs-ncu offset is end-of-kernel L2 dirty-line
// writeback drain serializing with the next graph replay; write-through
// moves the DRAM writes inside the launch where they overlap our reads.
// Predicted: in-kernel +1-2us, bench -2-3us. If neutral/worse, revert.

static constexpr int STEP    = 4;
static constexpr int THREADS = 1024;

__device__ __forceinline__ void lif_step(float4& mem, const float4 xin, float4& s) {
    mem.x = fmaf(mem.x, 0.25f, xin.x); mem.y = fmaf(mem.y, 0.25f, xin.y);
    mem.z = fmaf(mem.z, 0.25f, xin.z); mem.w = fmaf(mem.w, 0.25f, xin.w);
    s.x = mem.x > 0.5f ? 1.f : 0.f;  s.y = mem.y > 0.5f ? 1.f : 0.f;
    s.z = mem.z > 0.5f ? 1.f : 0.f;  s.w = mem.w > 0.5f ? 1.f : 0.f;
    mem.x = s.x > 0.f ? 0.f : mem.x; mem.y = s.y > 0.f ? 0.f : mem.y;
    mem.z = s.z > 0.f ? 0.f : mem.z; mem.w = s.w > 0.f ? 0.f : mem.w;
}

__global__ __launch_bounds__(THREADS)
void lif_fwd_kernel(const float4* __restrict__ x, float4* __restrict__ out, int n4) {
    int i = blockIdx.x * THREADS + threadIdx.x;
    if (i >= n4) return;

    // 4 independent front-batched LDG.128 (one per time step), evict-first.
    float4 x0 = __ldcs(&x[0 * (size_t)n4 + i]);
    float4 x1 = __ldcs(&x[1 * (size_t)n4 + i]);
    float4 x2 = __ldcs(&x[2 * (size_t)n4 + i]);
    float4 x3 = __ldcs(&x[3 * (size_t)n4 + i]);

    float4 mem = make_float4(0.f, 0.f, 0.f, 0.f);
    float4 s;

    lif_step(mem, x0, s);
    __stwt(&out[0 * (size_t)n4 + i], s);

    lif_step(mem, x1, s);
    __stwt(&out[1 * (size_t)n4 + i], s);

    lif_step(mem, x2, s);
    __stwt(&out[2 * (size_t)n4 + i], s);

    lif_step(mem, x3, s);
    __stwt(&out[3 * (size_t)n4 + i], s);
}

extern "C" void kernel_launch(void* const* d_in, const int* in_sizes, int n_in,
                              void* d_out, int out_size) {
    const float* x = (const float*)d_in[0];
    float* out = (float*)d_out;

    int total = in_sizes[0];          // STEP * N
    int n = total / STEP;             // 8,388,608 elements per step
    int n4 = n / 4;                   // 2,097,152 float4 per step

    int blocks = (n4 + THREADS - 1) / THREADS;  // 2048
    lif_fwd_kernel<<<blocks, THREADS>>>((const float4*)x, (float4*)out, n4);
}

// round 14
// speedup vs baseline: 1.0256x; 1.0256x over previous
#include <cuda_runtime.h>
#include <cstdint>

// LIF forward scan, 4 time steps. x/out: [4, N] fp32, N = 8,388,608.
// Forward value of the surrogate spike == hard threshold (mem > 0.5):
// stop_gradient(out_s - out_bp) + out_bp evaluates to out_s forward;
// the tanh surrogate only shapes gradients. V_TH=1 => mem/V_TH>0.5 <=> mem>0.5.
//
// FINAL KERNEL (measured best: 43.46us bench / 35.7us in-kernel,
// 7.52 TB/s effective = 94% of spec; pure HBM-bound stream, 134 MiB
// read + 134 MiB write). Config conclusions from R4-R12 sweeps:
//  - flat grid, 1024-thread blocks (2048 CTAs): fresh CTAs keep the
//    L1tex queue fed with front-batched loads; persistent grid-stride
//    de-batches loads behind stores + loop branch (-8% at ANY occupancy).
//  - 1 float4/thread, 30 regs, 2048 thr/SM; 2x coarsening costs a CTA/SM.
//  - evict-first (.cs) loads AND stores: zero reuse either direction;
//    evict-normal stores pollute L2 (-15%); .wt neutral (L2 already
//    streams writebacks eagerly); .cg loads neutral (L1tex queue work
//    is allocation-policy-invariant on sm_103a).

static constexpr int STEP    = 4;
static constexpr int THREADS = 1024;

__device__ __forceinline__ void lif_step(float4& mem, const float4 xin, float4& s) {
    mem.x = fmaf(mem.x, 0.25f, xin.x); mem.y = fmaf(mem.y, 0.25f, xin.y);
    mem.z = fmaf(mem.z, 0.25f, xin.z); mem.w = fmaf(mem.w, 0.25f, xin.w);
    s.x = mem.x > 0.5f ? 1.f : 0.f;  s.y = mem.y > 0.5f ? 1.f : 0.f;
    s.z = mem.z > 0.5f ? 1.f : 0.f;  s.w = mem.w > 0.5f ? 1.f : 0.f;
    mem.x = s.x > 0.f ? 0.f : mem.x; mem.y = s.y > 0.f ? 0.f : mem.y;
    mem.z = s.z > 0.f ? 0.f : mem.z; mem.w = s.w > 0.f ? 0.f : mem.w;
}

__global__ __launch_bounds__(THREADS)
void lif_fwd_kernel(const float4* __restrict__ x, float4* __restrict__ out, int n4) {
    int i = blockIdx.x * THREADS + threadIdx.x;
    if (i >= n4) return;

    // 4 independent front-batched LDG.128 (one per time step), evict-first.
    float4 x0 = __ldcs(&x[0 * (size_t)n4 + i]);
    float4 x1 = __ldcs(&x[1 * (size_t)n4 + i]);
    float4 x2 = __ldcs(&x[2 * (size_t)n4 + i]);
    float4 x3 = __ldcs(&x[3 * (size_t)n4 + i]);

    float4 mem = make_float4(0.f, 0.f, 0.f, 0.f);
    float4 s;

    lif_step(mem, x0, s);
    __stcs(&out[0 * (size_t)n4 + i], s);

    lif_step(mem, x1, s);
    __stcs(&out[1 * (size_t)n4 + i], s);

    lif_step(mem, x2, s);
    __stcs(&out[2 * (size_t)n4 + i], s);

    lif_step(mem, x3, s);
    __stcs(&out[3 * (size_t)n4 + i], s);
}

extern "C" void kernel_launch(void* const* d_in, const int* in_sizes, int n_in,
                              void* d_out, int out_size) {
    const float* x = (const float*)d_in[0];
    float* out = (float*)d_out;

    int total = in_sizes[0];          // STEP * N
    int n = total / STEP;             // 8,388,608 elements per step
    int n4 = n / 4;                   // 2,097,152 float4 per step

    int blocks = (n4 + THREADS - 1) / THREADS;  // 2048
    lif_fwd_kernel<<<blocks, THREADS>>>((const float4*)x, (float4*)out, n4);
}